// round 12
// baseline (speedup 1.0000x reference)
#include <cuda_runtime.h>
#include <cuda_bf16.h>

// Problem constants: N=4096 atoms, M=64 neighbors, Q=64, H=64, T=4 types
#define NATOMS 4096
#define MNBR   64
#define QD     64
#define HD     64

#define PREP_BLOCKS    128
#define ATOMS_PER_PREP 32
#define APB            4
#define SBLOCKS        (NATOMS / APB)          // 1024 stream blocks
#define TOTAL_BLOCKS   (PREP_BLOCKS + SBLOCKS) // 1152

// Scratch (rewritten fully every launch -> deterministic).
__device__ float        g_de[NATOMS * QD];
__device__ float        g_w[NATOMS * MNBR];
__device__ float        g_partials[3 * SBLOCKS];
__device__ unsigned int g_ticket = 0u;           // reset by last stream block
__device__ int          g_flag[PREP_BLOCKS];     // reset by last stream block

// ---------------------------------------------------------------------------
// ONE kernel, two roles. Blocks 0..127: prep (w + de for 32 atoms, then flag).
// Blocks 128..1151: stream (prefetch -> wait flag -> proven mainloop).
// Prep blocks are the first 128 bids -> all in wave 1 -> no deadlock.
// ---------------------------------------------------------------------------
__global__ __launch_bounds__(192) void tnep_all(
    const float* __restrict__ desc,     // [N, Q]
    const float* __restrict__ grads,    // [N, M, 3, Q]
    const float* __restrict__ pos,      // [N, 3]
    const float* __restrict__ box,      // [3, 3]
    const float* __restrict__ W0,       // [T, Q, H]
    const float* __restrict__ b0,       // [T, H]
    const float* __restrict__ W1,       // [T, H]
    const int*   __restrict__ Z,        // [N]
    const int*   __restrict__ gidx,     // [N, M]
    float*       __restrict__ out)      // [3]
{
    __shared__ float gj_s[ATOMS_PER_PREP * HD];   // 8 KB (prep role)
    __shared__ int   z_s[ATOMS_PER_PREP];
    __shared__ float de_s[APB * QD];              // stream role
    __shared__ float w_s[APB * MNBR];
    __shared__ float sval[12];
    __shared__ float wsum[6];
    __shared__ int   is_last_s;

    const int tid = threadIdx.x;

    if (blockIdx.x < PREP_BLOCKS) {
        // ================= PREP ROLE =================
        const int atom0 = blockIdx.x * ATOMS_PER_PREP;

        // ---- w phase: 2048 (i,m) pairs ----
        {
            const float b00 = box[0], b01 = box[1], b02 = box[2];
            const float b10 = box[3], b11 = box[4], b12 = box[5];
            const float b20 = box[6], b21 = box[7], b22 = box[8];
            const float det = b00 * (b11 * b22 - b12 * b21)
                            - b01 * (b10 * b22 - b12 * b20)
                            + b02 * (b10 * b21 - b11 * b20);
            const float rd = 1.0f / det;
            const float i00 = (b11 * b22 - b12 * b21) * rd, i01 = (b02 * b21 - b01 * b22) * rd, i02 = (b01 * b12 - b02 * b11) * rd;
            const float i10 = (b12 * b20 - b10 * b22) * rd, i11 = (b00 * b22 - b02 * b20) * rd, i12 = (b02 * b10 - b00 * b12) * rd;
            const float i20 = (b10 * b21 - b11 * b20) * rd, i21 = (b01 * b20 - b00 * b21) * rd, i22 = (b00 * b11 - b01 * b10) * rd;

            for (int g = 0; g < 11; g++) {
                const int p = g * 192 + tid;
                if (p < ATOMS_PER_PREP * MNBR) {
                    const int i = atom0 + (p >> 6);
                    const int j = gidx[(size_t)atom0 * MNBR + p];
                    const float dx = pos[j * 3 + 0] - pos[i * 3 + 0];
                    const float dy = pos[j * 3 + 1] - pos[i * 3 + 1];
                    const float dz = pos[j * 3 + 2] - pos[i * 3 + 2];
                    float s0 = dx * i00 + dy * i10 + dz * i20;
                    float s1 = dx * i01 + dy * i11 + dz * i21;
                    float s2 = dx * i02 + dy * i12 + dz * i22;
                    s0 -= rintf(s0); s1 -= rintf(s1); s2 -= rintf(s2);  // jnp.round
                    const float e0 = s0 * b00 + s1 * b10 + s2 * b20;
                    const float e1 = s0 * b01 + s1 * b11 + s2 * b21;
                    const float e2 = s0 * b02 + s1 * b12 + s2 * b22;
                    float r2 = e0 * e0 + e1 * e1 + e2 * e2;
                    if (j == i) r2 = 0.0f;                 // diagonal mask
                    g_w[(size_t)atom0 * MNBR + p] = -r2;   // minus folded in
                }
            }
        }

        if (tid < ATOMS_PER_PREP) z_s[tid] = Z[atom0 + tid];
        __syncthreads();

        // ---- step A: 16 threads per atom, float4 column dots (L1 W0) ----
        {
            const int c4 = tid & 15;              // 4 output columns 4c4..4c4+3
            #pragma unroll
            for (int pp = 0; pp < 3; pp++) {
                const int slot = pp * 12 + (tid >> 4);   // 0..35
                if (slot < ATOMS_PER_PREP) {
                    const int i = atom0 + slot;
                    const int z = z_s[slot];
                    const float4* __restrict__ W0z4 =
                        reinterpret_cast<const float4*>(W0 + (size_t)z * QD * HD);
                    const float4* __restrict__ di4 =
                        reinterpret_cast<const float4*>(desc + (size_t)i * QD);
                    float4 acc = make_float4(0.f, 0.f, 0.f, 0.f);
                    #pragma unroll
                    for (int q4i = 0; q4i < 16; q4i++) {
                        const float4 d = di4[q4i];
                        float4 w;
                        w = W0z4[(q4i * 4 + 0) * 16 + c4];
                        acc.x += d.x * w.x; acc.y += d.x * w.y; acc.z += d.x * w.z; acc.w += d.x * w.w;
                        w = W0z4[(q4i * 4 + 1) * 16 + c4];
                        acc.x += d.y * w.x; acc.y += d.y * w.y; acc.z += d.y * w.z; acc.w += d.y * w.w;
                        w = W0z4[(q4i * 4 + 2) * 16 + c4];
                        acc.x += d.z * w.x; acc.y += d.z * w.y; acc.z += d.z * w.z; acc.w += d.z * w.w;
                        w = W0z4[(q4i * 4 + 3) * 16 + c4];
                        acc.x += d.w * w.x; acc.y += d.w * w.y; acc.z += d.w * w.z; acc.w += d.w * w.w;
                    }
                    const float4 bv = reinterpret_cast<const float4*>(b0 + z * HD)[c4];
                    const float4 w1 = reinterpret_cast<const float4*>(W1 + z * HD)[c4];
                    const float h0 = tanhf(acc.x + bv.x);
                    const float h1 = tanhf(acc.y + bv.y);
                    const float h2 = tanhf(acc.z + bv.z);
                    const float h3 = tanhf(acc.w + bv.w);
                    float4 gj;
                    gj.x = (1.0f - h0 * h0) * w1.x;
                    gj.y = (1.0f - h1 * h1) * w1.y;
                    gj.z = (1.0f - h2 * h2) * w1.z;
                    gj.w = (1.0f - h3 * h3) * w1.w;
                    reinterpret_cast<float4*>(gj_s + slot * HD)[c4] = gj;
                }
            }
        }
        __syncthreads();

        // ---- step B: 4-lane-group float4 row dots (verified round 8) ----
        {
            const int gg  = tid >> 2;             // 0..47: row group
            const int lin = tid & 3;              // lane in group
            for (int row = gg; row < ATOMS_PER_PREP * QD; row += 48) {
                const int a = row >> 6, q = row & 63;
                const float4* __restrict__ rp = reinterpret_cast<const float4*>(
                    W0 + (size_t)z_s[a] * QD * HD + q * HD) + lin * 4;
                const float4* __restrict__ gv =
                    reinterpret_cast<const float4*>(gj_s + a * HD) + lin * 4;
                float v = 0.f;
                #pragma unroll
                for (int k = 0; k < 4; k++) {
                    const float4 t = rp[k];
                    const float4 g = gv[k];
                    v += t.x * g.x + t.y * g.y + t.z * g.z + t.w * g.w;
                }
                v += __shfl_down_sync(0xffffffffu, v, 2, 4);
                v += __shfl_down_sync(0xffffffffu, v, 1, 4);
                if (lin == 0) g_de[(size_t)(atom0 + a) * QD + q] = v;
            }
        }

        // ---- publish: fence then flag ----
        __threadfence();
        __syncthreads();
        if (tid == 0) ((volatile int*)g_flag)[blockIdx.x] = 1;
        return;
    }

    // ================= STREAM ROLE (proven 36us mainloop) =================
    const int sb    = blockIdx.x - PREP_BLOCKS;
    const int atom0 = sb * APB;

    // --- issue first 8 grad loads immediately (before the wait!) ---
    const float4* __restrict__ g4 =
        reinterpret_cast<const float4*>(grads) + (size_t)atom0 * 3072;
    float4 buf[8];
    #pragma unroll
    for (int k = 0; k < 8; k++) buf[k] = g4[k * 192 + tid];

    // --- wait for this block's prep producer ---
    if (tid == 0) {
        while (((volatile int*)g_flag)[sb >> 3] == 0) __nanosleep(64);
    }
    __syncthreads();
    __threadfence();   // order following loads after the flag observation

    // --- stage this block's de and w slices (coalesced) ---
    #pragma unroll
    for (int idx = tid; idx < APB * 64; idx += 192) {
        de_s[idx] = g_de[(size_t)atom0 * QD + idx];
        w_s[idx]  = g_w[(size_t)atom0 * MNBR + idx];
    }
    __syncthreads();

    const int e4    = tid % 48;
    const int m_off = tid / 48;
    const int q4    = e4 & 15;
    float carry = 0.0f;
    float4 acc = make_float4(0.f, 0.f, 0.f, 0.f);

    #pragma unroll
    for (int a = 0; a < APB; a++) {
        #pragma unroll
        for (int k = 0; k < 16; k++) {
            const int it = a * 16 + k;
            const float4 g = buf[it & 7];
            if (it + 8 < APB * 16)     // compile-time after full unroll
                buf[it & 7] = g4[((it + 8) >> 4) * 3072 + ((it + 8) & 15) * 192 + tid];
            const float w = w_s[a * 64 + k * 4 + m_off];
            acc.x += w * g.x; acc.y += w * g.y; acc.z += w * g.z; acc.w += w * g.w;
        }
        carry += acc.x * de_s[a * 64 + q4 * 4 + 0]
               + acc.y * de_s[a * 64 + q4 * 4 + 1]
               + acc.z * de_s[a * 64 + q4 * 4 + 2]
               + acc.w * de_s[a * 64 + q4 * 4 + 3];
        acc = make_float4(0.f, 0.f, 0.f, 0.f);
    }

    // --- per-block tail: 16-lane group reduce (channel-uniform groups) ---
    #pragma unroll
    for (int off = 8; off >= 1; off >>= 1)
        carry += __shfl_down_sync(0xffffffffu, carry, off, 16);
    const int lane = tid & 31;
    const int warp = tid >> 5;
    if ((lane & 15) == 0) sval[warp * 2 + (lane >> 4)] = carry;  // group g -> channel g%3
    __syncthreads();

    if (tid == 0) {
        float p0 = 0.f, p1 = 0.f, p2 = 0.f;
        #pragma unroll
        for (int g = 0; g < 12; g += 3) {
            p0 += sval[g + 0];
            p1 += sval[g + 1];
            p2 += sval[g + 2];
        }
        g_partials[0 * SBLOCKS + sb] = p0;
        g_partials[1 * SBLOCKS + sb] = p1;
        g_partials[2 * SBLOCKS + sb] = p2;
        __threadfence();
        const unsigned int t = atomicAdd(&g_ticket, 1u);
        is_last_s = (t == (unsigned)(SBLOCKS - 1)) ? 1 : 0;
    }
    __syncthreads();

    // --- last stream block: final reduction + reset handshake state ---
    if (is_last_s) {
        __threadfence();
        const int c  = tid >> 6;          // 0..2 (warps channel-uniform)
        const int j0 = tid & 63;
        const float* pc = g_partials + c * SBLOCKS;
        float a = 0.f;
        #pragma unroll 4
        for (int j = j0; j < SBLOCKS; j += 64) a += pc[j];
        #pragma unroll
        for (int off = 16; off >= 1; off >>= 1)
            a += __shfl_down_sync(0xffffffffu, a, off);
        if ((tid & 31) == 0) wsum[tid >> 5] = a;
        __syncthreads();
        if (tid < 3) out[tid] = wsum[2 * tid] + wsum[2 * tid + 1];
        if (tid < PREP_BLOCKS) g_flag[tid] = 0;   // reset for next replay
        if (tid == 0) g_ticket = 0u;
    }
}

extern "C" void kernel_launch(void* const* d_in, const int* in_sizes, int n_in,
                              void* d_out, int out_size) {
    const float* descriptors = (const float*)d_in[0];   // [4096, 64]
    const float* gradients   = (const float*)d_in[1];   // [4096, 64, 3, 64]
    const float* positions   = (const float*)d_in[2];   // [4096, 3]
    const float* box         = (const float*)d_in[3];   // [3, 3]
    const float* W0          = (const float*)d_in[4];   // [4, 64, 64]
    const float* b0          = (const float*)d_in[5];   // [4, 64]
    const float* W1          = (const float*)d_in[6];   // [4, 64]
    const int*   Z           = (const int*)d_in[7];     // [4096]
    const int*   grad_index  = (const int*)d_in[8];     // [4096, 64]
    float* out = (float*)d_out;                         // [3]

    tnep_all<<<TOTAL_BLOCKS, 192>>>(descriptors, gradients, positions, box,
                                    W0, b0, W1, Z, grad_index, out);
}

// round 15
// speedup vs baseline: 1.5362x; 1.5362x over previous
#include <cuda_runtime.h>
#include <cuda_bf16.h>
#include <cuda_pipeline.h>

// Problem constants: N=4096 atoms, M=64 neighbors, Q=64, H=64, T=4 types
#define NATOMS 4096
#define MNBR   64
#define QD     64
#define HD     64

#define APB     4                 // atoms per block
#define SBLOCKS (NATOMS / APB)    // 1024 blocks
#define RING    8                 // smem ring stages (7 in flight)

// Scratch (rewritten fully every launch -> deterministic).
__device__ float        g_partials[3 * SBLOCKS];
__device__ unsigned int g_ticket = 0u;     // reset by last block each launch

// ---------------------------------------------------------------------------
// ONE kernel: 1024 blocks x 192 threads, 4 atoms each.
// Prefetch via cp.async into an 8-stage smem ring (no register window!).
// Prologue (round-8-verified): w = -r2, step A (coalesced column dots),
// step B (4-lane-group float4 row dots) -> all into smem.
// Mainloop: per-thread LDS.128 from ring + FMA; per-thread commit groups.
// ---------------------------------------------------------------------------
__global__ __launch_bounds__(192) void tnep_fused(
    const float* __restrict__ desc,     // [N, Q]
    const float* __restrict__ grads,    // [N, M, 3, Q]
    const float* __restrict__ pos,      // [N, 3]
    const float* __restrict__ box,      // [3, 3]
    const float* __restrict__ W0,       // [T, Q, H]
    const float* __restrict__ b0,       // [T, H]
    const float* __restrict__ W1,       // [T, H]
    const int*   __restrict__ Z,        // [N]
    const int*   __restrict__ gidx,     // [N, M]
    float*       __restrict__ out)      // [3]
{
    __shared__ float4 ring[RING * 192];           // 24 KB grad staging
    __shared__ float  gj_s[APB * HD];
    __shared__ float  de_s[APB * QD];
    __shared__ float  w_s[APB * MNBR];
    __shared__ int    z_s[APB];
    __shared__ float  sval[12];
    __shared__ float  wsum[6];
    __shared__ int    is_last_s;

    const int tid   = threadIdx.x;
    const int atom0 = blockIdx.x * APB;

    // ---- (1) kick off 7 cp.async stages immediately (zero register cost) ----
    const float4* __restrict__ g4 =
        reinterpret_cast<const float4*>(grads) + (size_t)atom0 * 3072;
    #pragma unroll
    for (int s = 0; s < RING - 1; s++) {
        __pipeline_memcpy_async(&ring[s * 192 + tid], &g4[s * 192 + tid], 16);
        __pipeline_commit();
    }

    if (tid < APB) z_s[tid] = Z[atom0 + tid];

    // ---- (2) w = -r2 for this block's 256 (atom, m) pairs ----
    {
        const float b00 = box[0], b01 = box[1], b02 = box[2];
        const float b10 = box[3], b11 = box[4], b12 = box[5];
        const float b20 = box[6], b21 = box[7], b22 = box[8];
        const float det = b00 * (b11 * b22 - b12 * b21)
                        - b01 * (b10 * b22 - b12 * b20)
                        + b02 * (b10 * b21 - b11 * b20);
        const float rd = 1.0f / det;
        const float i00 = (b11 * b22 - b12 * b21) * rd, i01 = (b02 * b21 - b01 * b22) * rd, i02 = (b01 * b12 - b02 * b11) * rd;
        const float i10 = (b12 * b20 - b10 * b22) * rd, i11 = (b00 * b22 - b02 * b20) * rd, i12 = (b02 * b10 - b00 * b12) * rd;
        const float i20 = (b10 * b21 - b11 * b20) * rd, i21 = (b01 * b20 - b00 * b21) * rd, i22 = (b00 * b11 - b01 * b10) * rd;

        #pragma unroll
        for (int r = 0; r < 2; r++) {
            const int p = r * 192 + tid;          // 0..255 (2nd pass: tid<64)
            if (p < APB * MNBR) {
                const int i = atom0 + (p >> 6);
                const int j = gidx[(size_t)atom0 * MNBR + p];
                const float dx = pos[j * 3 + 0] - pos[i * 3 + 0];
                const float dy = pos[j * 3 + 1] - pos[i * 3 + 1];
                const float dz = pos[j * 3 + 2] - pos[i * 3 + 2];
                float s0 = dx * i00 + dy * i10 + dz * i20;
                float s1 = dx * i01 + dy * i11 + dz * i21;
                float s2 = dx * i02 + dy * i12 + dz * i22;
                s0 -= rintf(s0); s1 -= rintf(s1); s2 -= rintf(s2);  // jnp.round
                const float e0 = s0 * b00 + s1 * b10 + s2 * b20;
                const float e1 = s0 * b01 + s1 * b11 + s2 * b21;
                const float e2 = s0 * b02 + s1 * b12 + s2 * b22;
                float r2 = e0 * e0 + e1 * e1 + e2 * e2;
                if (j == i) r2 = 0.0f;            // diagonal mask
                w_s[p] = -r2;                     // dipole minus sign folded in
            }
        }
    }

    // ---- (3) step A: gj for 256 (atom, j) pairs; coalesced W0 columns ----
    #pragma unroll
    for (int r = 0; r < 2; r++) {
        const int x = r * 192 + tid;
        if (x < APB * HD) {
            const int a = x >> 6, j = x & 63;
            const int i = atom0 + a;
            const int z = Z[i];                   // warp-uniform broadcast
            const float* __restrict__ W0z = W0 + (size_t)z * QD * HD;
            const float* __restrict__ di  = desc + (size_t)i * QD;
            float s0 = 0.f, s1 = 0.f;
            #pragma unroll
            for (int q = 0; q < QD; q += 2) {
                s0 += di[q]     * W0z[q * HD + j];
                s1 += di[q + 1] * W0z[(q + 1) * HD + j];
            }
            const float s = s0 + s1 + b0[z * HD + j];
            const float h = tanhf(s);
            gj_s[x] = (1.0f - h * h) * W1[z * HD + j];
        }
    }
    __syncthreads();   // publishes gj_s + z_s (w_s also done)

    // ---- (4) step B: de[row] via 4-lane-group float4 row dots ----
    {
        const int warp = tid >> 5;
        const int lane = tid & 31;
        const int grp  = lane >> 2;               // 0..7
        const int lin  = lane & 3;                // lane in 4-group
        for (int r0 = warp * 8; r0 < APB * QD; r0 += 48) {   // warp-uniform trip
            const int row = r0 + grp;             // (a,q) flat index
            const int a   = row >> 6, q = row & 63;
            const float4* __restrict__ rp = reinterpret_cast<const float4*>(
                W0 + (size_t)z_s[a] * QD * HD + q * HD) + lin * 4;
            const float* __restrict__ gj = gj_s + a * 64 + lin * 16;
            float v = 0.f;
            #pragma unroll
            for (int k = 0; k < 4; k++) {
                const float4 t = rp[k];
                v += t.x * gj[k * 4 + 0] + t.y * gj[k * 4 + 1]
                   + t.z * gj[k * 4 + 2] + t.w * gj[k * 4 + 3];
            }
            v += __shfl_down_sync(0xffffffffu, v, 2, 4);
            v += __shfl_down_sync(0xffffffffu, v, 1, 4);
            if (lin == 0) de_s[row] = v;
        }
    }
    __syncthreads();   // publishes de_s

    // ---- mainloop: 64 chunks, smem ring, 7 stages in flight ----
    const int e4    = tid % 48;
    const int m_off = tid / 48;
    const int q4    = e4 & 15;
    float carry = 0.0f;
    float4 acc = make_float4(0.f, 0.f, 0.f, 0.f);

    #pragma unroll
    for (int a = 0; a < APB; a++) {
        #pragma unroll
        for (int k = 0; k < 16; k++) {
            const int it = a * 16 + k;
            __pipeline_wait_prior(6);             // stage `it` is ready
            const float4 g = ring[(it & 7) * 192 + tid];
            if (it + 7 < APB * 16) {              // compile-time after unroll
                const int nx = it + 7;
                __pipeline_memcpy_async(&ring[(nx & 7) * 192 + tid],
                                        &g4[(nx >> 4) * 3072 + (nx & 15) * 192 + tid], 16);
            }
            __pipeline_commit();                  // empty group in drain tail
            const float w = w_s[a * 64 + k * 4 + m_off];
            acc.x += w * g.x; acc.y += w * g.y; acc.z += w * g.z; acc.w += w * g.w;
        }
        carry += acc.x * de_s[a * 64 + q4 * 4 + 0]
               + acc.y * de_s[a * 64 + q4 * 4 + 1]
               + acc.z * de_s[a * 64 + q4 * 4 + 2]
               + acc.w * de_s[a * 64 + q4 * 4 + 3];
        acc = make_float4(0.f, 0.f, 0.f, 0.f);
    }

    // ---- per-block tail: 16-lane group reduce (channel-uniform groups) ----
    #pragma unroll
    for (int off = 8; off >= 1; off >>= 1)
        carry += __shfl_down_sync(0xffffffffu, carry, off, 16);
    const int lane = tid & 31;
    const int warp = tid >> 5;
    if ((lane & 15) == 0) sval[warp * 2 + (lane >> 4)] = carry;  // group g -> channel g%3
    __syncthreads();

    if (tid == 0) {
        float p0 = 0.f, p1 = 0.f, p2 = 0.f;
        #pragma unroll
        for (int g = 0; g < 12; g += 3) {
            p0 += sval[g + 0];
            p1 += sval[g + 1];
            p2 += sval[g + 2];
        }
        g_partials[0 * SBLOCKS + blockIdx.x] = p0;
        g_partials[1 * SBLOCKS + blockIdx.x] = p1;
        g_partials[2 * SBLOCKS + blockIdx.x] = p2;
        __threadfence();
        const unsigned int t = atomicAdd(&g_ticket, 1u);
        is_last_s = (t == (unsigned)(gridDim.x - 1)) ? 1 : 0;
    }
    __syncthreads();

    // ---- last block: fixed-order final reduction over 3 x 1024 partials ----
    if (is_last_s) {
        __threadfence();
        const int c  = tid >> 6;          // 0..2 (warps channel-uniform)
        const int j0 = tid & 63;
        const float* pc = g_partials + c * SBLOCKS;
        float a = 0.f;
        #pragma unroll 4
        for (int j = j0; j < SBLOCKS; j += 64) a += pc[j];
        #pragma unroll
        for (int off = 16; off >= 1; off >>= 1)
            a += __shfl_down_sync(0xffffffffu, a, off);
        if ((tid & 31) == 0) wsum[tid >> 5] = a;
        __syncthreads();
        if (tid < 3) out[tid] = wsum[2 * tid] + wsum[2 * tid + 1];
        if (tid == 0) g_ticket = 0u;      // reset for next graph replay
    }
}

extern "C" void kernel_launch(void* const* d_in, const int* in_sizes, int n_in,
                              void* d_out, int out_size) {
    const float* descriptors = (const float*)d_in[0];   // [4096, 64]
    const float* gradients   = (const float*)d_in[1];   // [4096, 64, 3, 64]
    const float* positions   = (const float*)d_in[2];   // [4096, 3]
    const float* box         = (const float*)d_in[3];   // [3, 3]
    const float* W0          = (const float*)d_in[4];   // [4, 64, 64]
    const float* b0          = (const float*)d_in[5];   // [4, 64]
    const float* W1          = (const float*)d_in[6];   // [4, 64]
    const int*   Z           = (const int*)d_in[7];     // [4096]
    const int*   grad_index  = (const int*)d_in[8];     // [4096, 64]
    float* out = (float*)d_out;                         // [3]

    tnep_fused<<<SBLOCKS, 192>>>(descriptors, gradients, positions, box,
                                 W0, b0, W1, Z, grad_index, out);
}

// round 17
// speedup vs baseline: 1.7724x; 1.1538x over previous
#include <cuda_runtime.h>
#include <cuda_bf16.h>

// Problem constants: N=4096 atoms, M=64 neighbors, Q=64, H=64, T=4 types
#define NATOMS 4096
#define MNBR   64
#define QD     64
#define HD     64

#define APB     4                 // atoms per block
#define SBLOCKS (NATOMS / APB)    // 1024 blocks -> ~1 wave at 7 blocks/SM

// Scratch (rewritten fully every launch -> deterministic).
__device__ float        g_partials[3 * SBLOCKS];
__device__ unsigned int g_ticket = 0u;     // reset by last block each launch

// ---------------------------------------------------------------------------
// ONE kernel: 1024 blocks x 192 threads, 4 atoms each.
// Structure: prologue FIRST (no grad loads live -> low regs), then the proven
// 8-deep LDG rolling-window streamer. Grid fits in ~one wave, so the prologue
// cost is paid once wall-clock (~2-4us), not per-block serially.
// ---------------------------------------------------------------------------
__global__ __launch_bounds__(192) void tnep_fused(
    const float* __restrict__ desc,     // [N, Q]
    const float* __restrict__ grads,    // [N, M, 3, Q]
    const float* __restrict__ pos,      // [N, 3]
    const float* __restrict__ box,      // [3, 3]
    const float* __restrict__ W0,       // [T, Q, H]
    const float* __restrict__ b0,       // [T, H]
    const float* __restrict__ W1,       // [T, H]
    const int*   __restrict__ Z,        // [N]
    const int*   __restrict__ gidx,     // [N, M]
    float*       __restrict__ out)      // [3]
{
    __shared__ float gj_s[APB * HD];
    __shared__ float de_s[APB * QD];
    __shared__ float w_s[APB * MNBR];
    __shared__ int   z_s[APB];
    __shared__ float sval[12];
    __shared__ float wsum[6];
    __shared__ int   is_last_s;

    const int tid   = threadIdx.x;
    const int atom0 = blockIdx.x * APB;

    if (tid < APB) z_s[tid] = Z[atom0 + tid];

    // ---- (1) w = -r2 for this block's 256 (atom, m) pairs ----
    // Issued first: the gidx->pos dependent gather has the longest latency.
    {
        const float b00 = box[0], b01 = box[1], b02 = box[2];
        const float b10 = box[3], b11 = box[4], b12 = box[5];
        const float b20 = box[6], b21 = box[7], b22 = box[8];
        const float det = b00 * (b11 * b22 - b12 * b21)
                        - b01 * (b10 * b22 - b12 * b20)
                        + b02 * (b10 * b21 - b11 * b20);
        const float rd = 1.0f / det;
        const float i00 = (b11 * b22 - b12 * b21) * rd, i01 = (b02 * b21 - b01 * b22) * rd, i02 = (b01 * b12 - b02 * b11) * rd;
        const float i10 = (b12 * b20 - b10 * b22) * rd, i11 = (b00 * b22 - b02 * b20) * rd, i12 = (b02 * b10 - b00 * b12) * rd;
        const float i20 = (b10 * b21 - b11 * b20) * rd, i21 = (b01 * b20 - b00 * b21) * rd, i22 = (b00 * b11 - b01 * b10) * rd;

        #pragma unroll
        for (int r = 0; r < 2; r++) {
            const int p = r * 192 + tid;          // 0..255 (2nd pass: tid<64)
            if (p < APB * MNBR) {
                const int i = atom0 + (p >> 6);
                const int j = gidx[(size_t)atom0 * MNBR + p];
                const float dx = pos[j * 3 + 0] - pos[i * 3 + 0];
                const float dy = pos[j * 3 + 1] - pos[i * 3 + 1];
                const float dz = pos[j * 3 + 2] - pos[i * 3 + 2];
                float s0 = dx * i00 + dy * i10 + dz * i20;
                float s1 = dx * i01 + dy * i11 + dz * i21;
                float s2 = dx * i02 + dy * i12 + dz * i22;
                s0 -= rintf(s0); s1 -= rintf(s1); s2 -= rintf(s2);  // jnp.round
                const float e0 = s0 * b00 + s1 * b10 + s2 * b20;
                const float e1 = s0 * b01 + s1 * b11 + s2 * b21;
                const float e2 = s0 * b02 + s1 * b12 + s2 * b22;
                float r2 = e0 * e0 + e1 * e1 + e2 * e2;
                if (j == i) r2 = 0.0f;            // diagonal mask
                w_s[p] = -r2;                     // dipole minus sign folded in
            }
        }
    }

    // ---- (2) step A: gj for 256 (atom, j) pairs; coalesced W0 columns ----
    #pragma unroll
    for (int r = 0; r < 2; r++) {
        const int x = r * 192 + tid;
        if (x < APB * HD) {
            const int a = x >> 6, j = x & 63;
            const int i = atom0 + a;
            const int z = Z[i];                   // warp-uniform broadcast
            const float* __restrict__ W0z = W0 + (size_t)z * QD * HD;
            const float* __restrict__ di  = desc + (size_t)i * QD;
            float s0 = 0.f, s1 = 0.f;
            #pragma unroll
            for (int q = 0; q < QD; q += 2) {
                s0 += di[q]     * W0z[q * HD + j];
                s1 += di[q + 1] * W0z[(q + 1) * HD + j];
            }
            const float s = s0 + s1 + b0[z * HD + j];
            const float h = tanhf(s);
            gj_s[x] = (1.0f - h * h) * W1[z * HD + j];
        }
    }
    __syncthreads();   // publishes gj_s + z_s (w_s also done)

    // ---- (3) step B: de[row] via 4-lane-group float4 row dots ----
    {
        const int warp = tid >> 5;
        const int lane = tid & 31;
        const int grp  = lane >> 2;               // 0..7
        const int lin  = lane & 3;                // lane in 4-group
        for (int r0 = warp * 8; r0 < APB * QD; r0 += 48) {   // warp-uniform trip
            const int row = r0 + grp;             // (a,q) flat index
            const int a   = row >> 6, q = row & 63;
            const float4* __restrict__ rp = reinterpret_cast<const float4*>(
                W0 + (size_t)z_s[a] * QD * HD + q * HD) + lin * 4;
            const float* __restrict__ gj = gj_s + a * 64 + lin * 16;
            float v = 0.f;
            #pragma unroll
            for (int k = 0; k < 4; k++) {
                const float4 t = rp[k];
                v += t.x * gj[k * 4 + 0] + t.y * gj[k * 4 + 1]
                   + t.z * gj[k * 4 + 2] + t.w * gj[k * 4 + 3];
            }
            v += __shfl_down_sync(0xffffffffu, v, 2, 4);
            v += __shfl_down_sync(0xffffffffu, v, 1, 4);
            if (lin == 0) de_s[row] = v;
        }
    }
    __syncthreads();   // publishes de_s -- prologue done, registers now free

    // ---- (4) mainloop: proven 8-deep LDG rolling-window streamer ----
    const float4* __restrict__ g4 =
        reinterpret_cast<const float4*>(grads) + (size_t)atom0 * 3072;
    float4 buf[8];
    #pragma unroll
    for (int k = 0; k < 8; k++) buf[k] = g4[k * 192 + tid];

    const int e4    = tid % 48;
    const int m_off = tid / 48;
    const int q4    = e4 & 15;
    float carry = 0.0f;
    float4 acc = make_float4(0.f, 0.f, 0.f, 0.f);

    #pragma unroll
    for (int a = 0; a < APB; a++) {
        #pragma unroll
        for (int k = 0; k < 16; k++) {
            const int it = a * 16 + k;
            const float4 g = buf[it & 7];
            if (it + 8 < APB * 16)     // compile-time after full unroll
                buf[it & 7] = g4[((it + 8) >> 4) * 3072 + ((it + 8) & 15) * 192 + tid];
            const float w = w_s[a * 64 + k * 4 + m_off];
            acc.x += w * g.x; acc.y += w * g.y; acc.z += w * g.z; acc.w += w * g.w;
        }
        carry += acc.x * de_s[a * 64 + q4 * 4 + 0]
               + acc.y * de_s[a * 64 + q4 * 4 + 1]
               + acc.z * de_s[a * 64 + q4 * 4 + 2]
               + acc.w * de_s[a * 64 + q4 * 4 + 3];
        acc = make_float4(0.f, 0.f, 0.f, 0.f);
    }

    // ---- per-block tail: 16-lane group reduce (channel-uniform groups) ----
    #pragma unroll
    for (int off = 8; off >= 1; off >>= 1)
        carry += __shfl_down_sync(0xffffffffu, carry, off, 16);
    const int lane = tid & 31;
    const int warp = tid >> 5;
    if ((lane & 15) == 0) sval[warp * 2 + (lane >> 4)] = carry;  // group g -> channel g%3
    __syncthreads();

    if (tid == 0) {
        float p0 = 0.f, p1 = 0.f, p2 = 0.f;
        #pragma unroll
        for (int g = 0; g < 12; g += 3) {
            p0 += sval[g + 0];
            p1 += sval[g + 1];
            p2 += sval[g + 2];
        }
        g_partials[0 * SBLOCKS + blockIdx.x] = p0;
        g_partials[1 * SBLOCKS + blockIdx.x] = p1;
        g_partials[2 * SBLOCKS + blockIdx.x] = p2;
        __threadfence();
        const unsigned int t = atomicAdd(&g_ticket, 1u);
        is_last_s = (t == (unsigned)(gridDim.x - 1)) ? 1 : 0;
    }
    __syncthreads();

    // ---- last block: fixed-order final reduction over 3 x 1024 partials ----
    if (is_last_s) {
        __threadfence();
        const int c  = tid >> 6;          // 0..2 (warps channel-uniform)
        const int j0 = tid & 63;
        const float* pc = g_partials + c * SBLOCKS;
        float a = 0.f;
        #pragma unroll 4
        for (int j = j0; j < SBLOCKS; j += 64) a += pc[j];
        #pragma unroll
        for (int off = 16; off >= 1; off >>= 1)
            a += __shfl_down_sync(0xffffffffu, a, off);
        if ((tid & 31) == 0) wsum[tid >> 5] = a;
        __syncthreads();
        if (tid < 3) out[tid] = wsum[2 * tid] + wsum[2 * tid + 1];
        if (tid == 0) g_ticket = 0u;      // reset for next graph replay
    }
}

extern "C" void kernel_launch(void* const* d_in, const int* in_sizes, int n_in,
                              void* d_out, int out_size) {
    const float* descriptors = (const float*)d_in[0];   // [4096, 64]
    const float* gradients   = (const float*)d_in[1];   // [4096, 64, 3, 64]
    const float* positions   = (const float*)d_in[2];   // [4096, 3]
    const float* box         = (const float*)d_in[3];   // [3, 3]
    const float* W0          = (const float*)d_in[4];   // [4, 64, 64]
    const float* b0          = (const float*)d_in[5];   // [4, 64]
    const float* W1          = (const float*)d_in[6];   // [4, 64]
    const int*   Z           = (const int*)d_in[7];     // [4096]
    const int*   grad_index  = (const int*)d_in[8];     // [4096, 64]
    float* out = (float*)d_out;                         // [3]

    tnep_fused<<<SBLOCKS, 192>>>(descriptors, gradients, positions, box,
                                 W0, b0, W1, Z, grad_index, out);
}